// round 13
// baseline (speedup 1.0000x reference)
#include <cuda_runtime.h>
#include <cstdint>

// Input:  x (2,8,256,256) fp32, F (3,3) fp32
// Output: (2,8,256,256) fp32 epipolar line-sum.
//
// Pipeline:
//  1) transpose_k : x -> g_t4[h][w][pg] (4-plane float4 chunks)
//  2) work_k      : blocks 0..255 = col+row P prefix tables (R9 shape)
//                   blocks 256..  = warp/pixel exact index + telescoped records
//  3) qderive_k   : Q[c][t] = P[c][t] - P[c-1][t]  (pointwise, no scan)
//  4) gather_k    : ONE table load per record (half the bytes of run scheme)
//     record = ci | t<<8 | neg<<17 | isQ<<18
//     out = -P[c_first][T0] + sum(+/-Q[c][t] at boundaries) + P[c_last][T1]

#define FULLM 0xffffffffu
#define S_TAB (256 * 257)
#define RCAP  272                                  // records/pixel capacity

__device__ float4   g_t4 [256 * 256 * 4];          // 4 MB repacked image
__device__ unsigned g_run[256 * 256 * RCAP];       // record stream
__device__ int      g_nrun[256 * 256];
__device__ float4   g_tab[4 * S_TAB * 4];          // [colP][colQ][rowP][rowQ]

__global__ void __launch_bounds__(256) transpose_k(const float* __restrict__ in) {
    int gid = blockIdx.x * 256 + threadIdx.x;
    int px = gid >> 2, pg = gid & 3;
    float4 o;
    o.x = __ldg(in + (pg * 4 + 0) * 65536 + px);
    o.y = __ldg(in + (pg * 4 + 1) * 65536 + px);
    o.z = __ldg(in + (pg * 4 + 2) * 65536 + px);
    o.w = __ldg(in + (pg * 4 + 3) * 65536 + px);
    g_t4[px * 4 + pg] = o;
}

// Warp-serial exclusive prefix of one (line, pg). is_col -> region 0, else region 2.
__device__ __forceinline__ void prefix_line(int line, int pg, bool is_col, int lane) {
    float4* __restrict__ Pt = g_tab + ((is_col ? 0 : 2) * S_TAB + line * 257) * 4;
    float4 carry = make_float4(0.f, 0.f, 0.f, 0.f);
    if (lane == 0) Pt[pg] = carry;
#pragma unroll
    for (int r = 0; r < 8; ++r) {
        int t = r * 32 + lane;
        int px = is_col ? (line * 256 + t) : (t * 256 + line);
        float4 s = __ldg(g_t4 + px * 4 + pg);
#pragma unroll
        for (int d = 1; d < 32; d <<= 1) {
            float ax = __shfl_up_sync(FULLM, s.x, d);
            float ay = __shfl_up_sync(FULLM, s.y, d);
            float az = __shfl_up_sync(FULLM, s.z, d);
            float aw = __shfl_up_sync(FULLM, s.w, d);
            if (lane >= d) { s.x += ax; s.y += ay; s.z += az; s.w += aw; }
        }
        Pt[(t + 1) * 4 + pg] =
            make_float4(carry.x + s.x, carry.y + s.y, carry.z + s.z, carry.w + s.w);
        carry.x += __shfl_sync(FULLM, s.x, 31);
        carry.y += __shfl_sync(FULLM, s.y, 31);
        carry.z += __shfl_sync(FULLM, s.z, 31);
        carry.w += __shfl_sync(FULLM, s.w, 31);
    }
}

// Q tables pointwise from P: Q[c][t] = P[c][t] - P[c-1][t]; Q[0][*] = 0.
// gid covers 2 regions x 256 c x 257 t x 4 pg.
__global__ void __launch_bounds__(256) qderive_k() {
    int gid = blockIdx.x * 256 + threadIdx.x;       // < 2*256*257*4 = 526336
    if (gid >= 2 * S_TAB * 4) return;
    int pg  = gid & 3;
    int rem = gid >> 2;                             // region*S_TAB + c*257 + t
    int reg = rem / S_TAB;                          // 0 = col, 1 = row
    int ct  = rem - reg * S_TAB;
    int c   = ct / 257;
    const float4* __restrict__ Pt = g_tab + (reg * 2 * S_TAB) * 4;   // P region
    float4* __restrict__ Qt = g_tab + ((reg * 2 + 1) * S_TAB) * 4;   // Q region
    float4 o = make_float4(0.f, 0.f, 0.f, 0.f);
    if (c > 0) {
        float4 a = __ldg(Pt + ct * 4 + pg);
        float4 b = __ldg(Pt + (ct - 257) * 4 + pg);
        o = make_float4(a.x - b.x, a.y - b.y, a.z - b.z, a.w - b.w);
    }
    Qt[ct * 4 + pg] = o;
}

// Warp per pixel: EXACT index arithmetic (R4..R12 — do not touch) + record emission.
__device__ __forceinline__ void idx_rle_pixel(const float* __restrict__ Fm,
                                              int px, int lane) {
    const int w = px & 255, h = px >> 8;
    const float u = (float)w, v = (float)h;

    const float F0 = __ldg(Fm+0), F1 = __ldg(Fm+1), F2 = __ldg(Fm+2);
    const float F3 = __ldg(Fm+3), F4 = __ldg(Fm+4), F5 = __ldg(Fm+5);
    const float F6 = __ldg(Fm+6), F7 = __ldg(Fm+7), F8 = __ldg(Fm+8);
    float A = __fadd_rn(__fmaf_rn(F3, v, __fmul_rn(F0, u)), F6);
    float B = __fadd_rn(__fmaf_rn(F4, v, __fmul_rn(F1, u)), F7);
    float C = __fadd_rn(__fmaf_rn(F5, v, __fmul_rn(F2, u)), F8);

    const bool col = (fabsf(B) >= fabsf(A));
    float P, Q;
    if (col) { P = A; Q = (fabsf(B) < 1e-8f) ? 1e-8f : B; }
    else     { P = B; Q = (fabsf(A) < 1e-8f) ? 1e-8f : A; }
    const float rq  = __frcp_rn(Q);
    const float nrq = -rq;

    unsigned vals[8];
    float tf = (float)(lane * 8);
#pragma unroll
    for (int j = 0; j < 8; ++j, tf += 1.0f) {
        float n  = __fmaf_rn(P, tf, C);
        float yf = __fmul_rn(n, nrq);
        int   ci = __float2int_rn(yf);
        float d  = yf - (float)ci;
        if (0.5f - fabsf(d) < 5e-4f) {
            ci = __float2int_rn(__fdiv_rn(-n, Q));
        }
        vals[j] = ((unsigned)ci < 256u) ? (unsigned)ci : 0xFFFFu;
    }

    unsigned prev = __shfl_up_sync(FULLM, vals[7], 1);
    if (lane == 0) prev = 0xFFFFu;                 // before t=0: invalid

    int cnt = 0;
    {
        unsigned p = prev;
#pragma unroll
        for (int k = 0; k < 8; ++k) {
            unsigned a = p, b = vals[k];
            if (a != b) {
                if (a == 0xFFFFu || b == 0xFFFFu) cnt += 1;
                else { int d = (int)b - (int)a; cnt += (d > 0) ? d : -d; }
            }
            p = b;
        }
    }
    if (lane == 31 && vals[7] != 0xFFFFu) cnt += 1;

    int off = cnt;
#pragma unroll
    for (int d = 1; d < 32; d <<= 1) {
        int o = __shfl_up_sync(FULLM, off, d);
        if (lane >= d) off += o;
    }
    int total = __shfl_sync(FULLM, off, 31);
    off -= cnt;
    if (lane == 31) g_nrun[px] = total;

    unsigned cur = (unsigned)px * RCAP + (unsigned)off;
    {
        unsigned p = prev;
#pragma unroll
        for (int k = 0; k < 8; ++k) {
            unsigned a = p, b = vals[k];
            unsigned t = (unsigned)(lane * 8 + k);
            if (a != b) {
                if (a == 0xFFFFu) {                  // start: -P[b][t]
                    g_run[cur++] = b | (t << 8) | (1u << 17);
                } else if (b == 0xFFFFu) {           // end:   +P[a][t]
                    g_run[cur++] = a | (t << 8);
                } else {
                    int d = (int)b - (int)a;
                    if (d > 0) {                     // up-steps: -Q[a+i][t]
                        for (int i = 1; i <= d; ++i)
                            g_run[cur++] = (a + (unsigned)i) | (t << 8) | (1u << 17) | (1u << 18);
                    } else {                         // down-steps: +Q[a-i][t]
                        for (int i = 0; i < -d; ++i)
                            g_run[cur++] = (a - (unsigned)i) | (t << 8) | (1u << 18);
                    }
                }
            }
            p = b;
        }
    }
    if (lane == 31 && vals[7] != 0xFFFFu)            // +P[c_last][256]
        g_run[cur++] = vals[7] | (256u << 8);
}

// blocks 0..255: 2048 P-prefix warps; blocks 256..8447: warp-per-pixel records
__global__ void __launch_bounds__(256) work_k(const float* __restrict__ Fm) {
    const int lane = threadIdx.x & 31;
    const int warp = threadIdx.x >> 5;
    if (blockIdx.x < 256) {
        int wg = blockIdx.x * 8 + warp;              // 0..2047
        prefix_line((wg >> 2) & 255, wg & 3, wg < 1024, lane);
    } else {
        int px = (blockIdx.x - 256) * 8 + warp;
        idx_rle_pixel(Fm, px, lane);
    }
}

// Block = 8x8 pixel tile. Warp = 8 pixels x 4 pg. ONE table load per record.
__global__ void __launch_bounds__(256) gather_k(const float* __restrict__ Fm,
                                                float* __restrict__ out) {
    const int lane = threadIdx.x & 31;
    const int warp = threadIdx.x >> 5;
    const int pg   = lane & 3;
    const int pix  = lane >> 2;
    const int h = blockIdx.x * 8 + warp;
    const int w = blockIdx.y * 8 + pix;
    const int px = h * 256 + w;
    const float u = (float)w, v = (float)h;

    // mode bit — exact same computation as idx_rle_pixel
    const float F0 = __ldg(Fm+0), F1 = __ldg(Fm+1);
    const float F3 = __ldg(Fm+3), F4 = __ldg(Fm+4);
    const float F6 = __ldg(Fm+6), F7 = __ldg(Fm+7);
    float A = __fadd_rn(__fmaf_rn(F3, v, __fmul_rn(F0, u)), F6);
    float B = __fadd_rn(__fmaf_rn(F4, v, __fmul_rn(F1, u)), F7);
    const bool col = (fabsf(B) >= fabsf(A));
    const float4* __restrict__ Tb = g_tab + (col ? 0 : 2 * S_TAB) * 4 + pg;

    int n = __ldg(g_nrun + px);
    int nmax = n;
#pragma unroll
    for (int d = 16; d; d >>= 1)
        nmax = max(nmax, __shfl_xor_sync(FULLM, nmax, d));

    const uint4* __restrict__ rv =
        reinterpret_cast<const uint4*>(g_run + (size_t)px * RCAP);

    float4 acc0 = make_float4(0.f, 0.f, 0.f, 0.f);
    float4 acc1 = make_float4(0.f, 0.f, 0.f, 0.f);
    uint4 V = make_uint4(0u, 0u, 0u, 0u);
    for (int j = 0; j < nmax; ++j) {
        if ((j & 3) == 0) V = __ldg(rv + (j >> 2));
        unsigned word = (j & 3) == 0 ? V.x : (j & 3) == 1 ? V.y
                       : (j & 3) == 2 ? V.z : V.w;
        if (j < n) {
            int   c  = word & 255;
            int   t  = (word >> 8) & 511;
            float s  = (word & (1u << 17)) ? -1.0f : 1.0f;
            int   kq = (word >> 18) & 1;
            float4 val = __ldg(Tb + (kq * S_TAB + c * 257 + t) * 4);
            if (j & 1) {
                acc1.x = __fmaf_rn(s, val.x, acc1.x);
                acc1.y = __fmaf_rn(s, val.y, acc1.y);
                acc1.z = __fmaf_rn(s, val.z, acc1.z);
                acc1.w = __fmaf_rn(s, val.w, acc1.w);
            } else {
                acc0.x = __fmaf_rn(s, val.x, acc0.x);
                acc0.y = __fmaf_rn(s, val.y, acc0.y);
                acc0.z = __fmaf_rn(s, val.z, acc0.z);
                acc0.w = __fmaf_rn(s, val.w, acc0.w);
            }
        }
    }
    float4 acc = make_float4(acc0.x + acc1.x, acc0.y + acc1.y,
                             acc0.z + acc1.z, acc0.w + acc1.w);

    out[(pg * 4 + 0) * 65536 + px] = acc.x;
    out[(pg * 4 + 1) * 65536 + px] = acc.y;
    out[(pg * 4 + 2) * 65536 + px] = acc.z;
    out[(pg * 4 + 3) * 65536 + px] = acc.w;
}

extern "C" void kernel_launch(void* const* d_in, const int* in_sizes, int n_in,
                              void* d_out, int out_size) {
    const float* img = (const float*)d_in[0];
    const float* F   = (const float*)d_in[1];
    if (n_in >= 2 && in_sizes[0] == 9) {             // defensive: input order swap
        img = (const float*)d_in[1];
        F   = (const float*)d_in[0];
    }
    float* out = (float*)d_out;

    transpose_k<<<1024, 256>>>(img);
    work_k<<<8448, 256>>>(F);
    qderive_k<<<2056, 256>>>();
    dim3 ggat(32, 32);
    gather_k<<<ggat, 256>>>(F, out);
}